// round 13
// baseline (speedup 1.0000x reference)
#include <cuda_runtime.h>
#include <cuda_bf16.h>
#include <mma.h>
#include <math.h>
#include <stdint.h>

using namespace nvcuda;

// Problem constants
#define BATCH 64
#define NATOM 512
#define DFEAT 128
#define DIMP  128
#define MROWS (BATCH * NATOM)      // 32768
#define NCOLS (2 * DIMP)           // 256 (q | k fused in n)
#define NTILES (MROWS / 128)       // 256 m-tiles (4 per batch)

// smem strides (elements)
#define ASTRIDE 40                 // 32 + 8 pad (bf16)
#define BSTRIDE 264                // 256 + 8 pad (bf16)
#define QSTRIDE 132                // 128 + 4 pad (fp32)

// stage layout (bytes, per buffer)
#define OFF_AH   0
#define OFF_AL   (128 * ASTRIDE * 2)                    // 10240
#define OFF_BH   (OFF_AL + 128 * ASTRIDE * 2)           // 20480
#define OFF_BL   (OFF_BH + 32 * BSTRIDE * 2)            // 37376
#define STAGE_BYTES (OFF_BL + 32 * BSTRIDE * 2)         // 54272
#define EPI_BYTES (2 * 128 * QSTRIDE * 4)               // 135168 (Qs | Ks)
#define PIPE_BYTES (2 * STAGE_BYTES)                    // 108544
#define DSMEM_BYTES (EPI_BYTES > PIPE_BYTES ? EPI_BYTES : PIPE_BYTES)

// Device scratch
__device__ float g_Kt[BATCH][DIMP][NATOM];             // compacted K^T, 16 MB
__device__ float g_qsum_part[NTILES][DIMP];            // 128 KB
__device__ float g_diag[MROWS];                        // 128 KB (compacted)
__device__ int   g_idx[BATCH][NATOM];                  // active-atom lists
__device__ int   g_cnt[BATCH];

// ---------------------------------------------------------------------------
// compact: per batch, order-preserving list of active (mask=1) atoms.
// ---------------------------------------------------------------------------
__global__ __launch_bounds__(512)
void compact_kernel(const float* __restrict__ mask) {
    const int b = blockIdx.x, tid = threadIdx.x;
    const int lane = tid & 31, warp = tid >> 5;
    __shared__ int wcnt[16];
    __shared__ int woff[16];

    const int m = mask[(size_t)b * NATOM + tid] > 0.5f ? 1 : 0;
    const unsigned bal = __ballot_sync(0xffffffffu, m);
    if (lane == 0) wcnt[warp] = __popc(bal);
    __syncthreads();
    if (tid == 0) {
        int s = 0;
        #pragma unroll
        for (int i = 0; i < 16; i++) { woff[i] = s; s += wcnt[i]; }
        g_cnt[b] = s;
    }
    __syncthreads();
    if (m) {
        int pos = woff[warp] + __popc(bal & ((1u << lane) - 1u));
        g_idx[b][pos] = tid;
    }
}

// ---------------------------------------------------------------------------
// Fused GEMM over COMPACTED rows: 256 CTAs x 512 threads, tile 128m x 256n,
// K=3x128 bf16 split, double-buffered. Tiles past cnt exit immediately.
// Epilogue: compacted K^T, qsum partials, diag.
// ---------------------------------------------------------------------------
__global__ __launch_bounds__(512, 1)
void gemm_fused_kernel(const float* __restrict__ A,
                       const float* __restrict__ Wq, const float* __restrict__ Wk,
                       const float* __restrict__ bq, const float* __restrict__ bk) {
    extern __shared__ char dsm[];
    __shared__ float validS[128];
    __shared__ int   idxS[128];
    __shared__ float partQ[4][DIMP];

    const int tid  = threadIdx.x;
    const int warp = tid >> 5;
    const int lane = tid & 31;
    const int mt   = blockIdx.x;
    const int b    = mt >> 2;
    const int slot = mt & 3;
    const int cnt  = g_cnt[b];

    // empty tile: publish zero qsum partial, leave
    if (slot * 128 >= cnt) {
        if (tid < DIMP) g_qsum_part[mt][tid] = 0.0f;
        return;
    }

    if (tid < 128) {
        int j = slot * 128 + tid;
        int ok = j < cnt;
        idxS[tid]   = ok ? g_idx[b][j] : g_idx[b][0];   // clamp (finite junk)
        validS[tid] = ok ? 1.0f : 0.0f;
    }

    const int wm = (warp >> 2) * 32;      // 4 warp-rows of 32
    const int wn = (warp & 3) * 64;       // 4 warp-cols of 64

    // --- accumulator init with bias (replicated 16-row tile in dsm) ---
    float* biasT = (float*)dsm;           // 16 x 256
    for (int i = tid; i < 16 * NCOLS; i += 512) {
        int col = i & 255;
        biasT[i] = (col < DIMP) ? bq[col] : bk[col - DIMP];
    }
    __syncthreads();

    wmma::fragment<wmma::accumulator, 16, 16, 16, float> acc[2][4];
    #pragma unroll
    for (int i = 0; i < 2; i++)
        #pragma unroll
        for (int j = 0; j < 4; j++)
            wmma::load_matrix_sync(acc[i][j], biasT + wn + j * 16, NCOLS, wmma::mem_row_major);
    __syncthreads();

    // loader index precompute (A rows gathered through idxS)
    const int ar0 = tid >> 3,          ac0 = (tid & 7) * 4;
    const int ar1 = (tid + 512) >> 3,  ac1 = ((tid + 512) & 7) * 4;
    const float* rp0 = A + ((size_t)b * NATOM + idxS[ar0]) * DFEAT;
    const float* rp1 = A + ((size_t)b * NATOM + idxS[ar1]) * DFEAT;
    int brr[4], bcc[4];
    #pragma unroll
    for (int v = 0; v < 4; v++) {
        int f = tid + v * 512;
        brr[v] = f >> 6;
        bcc[v] = (f & 63) * 4;
    }

    float4 pa[2], pb[4];
    #define FETCH(kc)                                                                   \
        do {                                                                            \
            pa[0] = *(const float4*)(rp0 + (kc) * 32 + ac0);                            \
            pa[1] = *(const float4*)(rp1 + (kc) * 32 + ac1);                            \
            _Pragma("unroll")                                                           \
            for (int v = 0; v < 4; v++) {                                               \
                int k = (kc) * 32 + brr[v];                                             \
                pb[v] = (bcc[v] < DIMP)                                                 \
                    ? *(const float4*)(Wq + (size_t)k * DIMP + bcc[v])                  \
                    : *(const float4*)(Wk + (size_t)k * DIMP + (bcc[v] - DIMP));        \
            }                                                                           \
        } while (0)

    #define CVT_STORE(buf)                                                              \
        do {                                                                            \
            __nv_bfloat16* AhS = (__nv_bfloat16*)(dsm + (buf) * STAGE_BYTES + OFF_AH);  \
            __nv_bfloat16* AlS = (__nv_bfloat16*)(dsm + (buf) * STAGE_BYTES + OFF_AL);  \
            __nv_bfloat16* BhS = (__nv_bfloat16*)(dsm + (buf) * STAGE_BYTES + OFF_BH);  \
            __nv_bfloat16* BlS = (__nv_bfloat16*)(dsm + (buf) * STAGE_BYTES + OFF_BL);  \
            _Pragma("unroll")                                                           \
            for (int v = 0; v < 2; v++) {                                               \
                float vv[4] = {pa[v].x, pa[v].y, pa[v].z, pa[v].w};                     \
                uint16_t h[4], l[4];                                                    \
                _Pragma("unroll")                                                       \
                for (int i = 0; i < 4; i++) {                                           \
                    __nv_bfloat16 hb = __float2bfloat16(vv[i]);                         \
                    __nv_bfloat16 lb = __float2bfloat16(vv[i] - __bfloat162float(hb));  \
                    h[i] = __bfloat16_as_ushort(hb);                                    \
                    l[i] = __bfloat16_as_ushort(lb);                                    \
                }                                                                       \
                int r = v ? ar1 : ar0, c = v ? ac1 : ac0;                               \
                *(uint2*)(&AhS[r * ASTRIDE + c]) =                                      \
                    make_uint2(((uint32_t)h[1] << 16) | h[0], ((uint32_t)h[3] << 16) | h[2]); \
                *(uint2*)(&AlS[r * ASTRIDE + c]) =                                      \
                    make_uint2(((uint32_t)l[1] << 16) | l[0], ((uint32_t)l[3] << 16) | l[2]); \
            }                                                                           \
            _Pragma("unroll")                                                           \
            for (int v = 0; v < 4; v++) {                                               \
                float vv[4] = {pb[v].x, pb[v].y, pb[v].z, pb[v].w};                     \
                uint16_t h[4], l[4];                                                    \
                _Pragma("unroll")                                                       \
                for (int i = 0; i < 4; i++) {                                           \
                    __nv_bfloat16 hb = __float2bfloat16(vv[i]);                         \
                    __nv_bfloat16 lb = __float2bfloat16(vv[i] - __bfloat162float(hb));  \
                    h[i] = __bfloat16_as_ushort(hb);                                    \
                    l[i] = __bfloat16_as_ushort(lb);                                    \
                }                                                                       \
                *(uint2*)(&BhS[brr[v] * BSTRIDE + bcc[v]]) =                            \
                    make_uint2(((uint32_t)h[1] << 16) | h[0], ((uint32_t)h[3] << 16) | h[2]); \
                *(uint2*)(&BlS[brr[v] * BSTRIDE + bcc[v]]) =                            \
                    make_uint2(((uint32_t)l[1] << 16) | l[0], ((uint32_t)l[3] << 16) | l[2]); \
            }                                                                           \
        } while (0)

    // --- pipelined mainloop: 4 chunks of k=32, 3 passes each ---
    FETCH(0);
    CVT_STORE(0);
    __syncthreads();

    #pragma unroll
    for (int kc = 0; kc < 4; kc++) {
        const int cur = kc & 1;
        if (kc < 3) FETCH(kc + 1);

        const __nv_bfloat16* AhS = (const __nv_bfloat16*)(dsm + cur * STAGE_BYTES + OFF_AH);
        const __nv_bfloat16* AlS = (const __nv_bfloat16*)(dsm + cur * STAGE_BYTES + OFF_AL);
        const __nv_bfloat16* BhS = (const __nv_bfloat16*)(dsm + cur * STAGE_BYTES + OFF_BH);
        const __nv_bfloat16* BlS = (const __nv_bfloat16*)(dsm + cur * STAGE_BYTES + OFF_BL);

        #pragma unroll
        for (int pass = 0; pass < 3; pass++) {
            const __nv_bfloat16* Ap = (pass == 1) ? AlS : AhS;
            const __nv_bfloat16* Bp = (pass == 2) ? BlS : BhS;
            #pragma unroll
            for (int kk = 0; kk < 32; kk += 16) {
                wmma::fragment<wmma::matrix_a, 16, 16, 16, __nv_bfloat16, wmma::row_major> af[2];
                wmma::fragment<wmma::matrix_b, 16, 16, 16, __nv_bfloat16, wmma::row_major> bf[4];
                #pragma unroll
                for (int i = 0; i < 2; i++)
                    wmma::load_matrix_sync(af[i], Ap + (wm + i * 16) * ASTRIDE + kk, ASTRIDE);
                #pragma unroll
                for (int j = 0; j < 4; j++)
                    wmma::load_matrix_sync(bf[j], Bp + kk * BSTRIDE + wn + j * 16, BSTRIDE);
                #pragma unroll
                for (int i = 0; i < 2; i++)
                    #pragma unroll
                    for (int j = 0; j < 4; j++)
                        wmma::mma_sync(acc[i][j], af[i], bf[j], acc[i][j]);
            }
        }

        if (kc < 3) CVT_STORE(1 - cur);
        __syncthreads();
    }

    // --- epilogue: overlay Qs|Ks in dsm ---
    float* Qs = (float*)dsm;                       // 128 x QSTRIDE
    float* Ks = Qs + 128 * QSTRIDE;
    #pragma unroll
    for (int i = 0; i < 2; i++) {
        #pragma unroll
        for (int j = 0; j < 4; j++) {
            int n = wn + j * 16;
            float* t = (n < DIMP) ? (Qs + (wm + i * 16) * QSTRIDE + n)
                                  : (Ks + (wm + i * 16) * QSTRIDE + (n - DIMP));
            wmma::store_matrix_sync(t, acc[i][j], QSTRIDE, wmma::mem_row_major);
        }
    }
    __syncthreads();

    // compacted K^T write: batch b, compacted slots ns..ns+127
    {
        const int ns = slot * 128;
        #pragma unroll
        for (int v = 0; v < 8; v++) {
            int f = v * 512 + tid;        // 0..4095
            int n = f & 127;
            int d4 = (f >> 7) * 4;        // 0..124
            float4 kv = *(float4*)(&Ks[n * QSTRIDE + d4]);
            g_Kt[b][d4 + 0][ns + n] = kv.x;
            g_Kt[b][d4 + 1][ns + n] = kv.y;
            g_Kt[b][d4 + 2][ns + n] = kv.z;
            g_Kt[b][d4 + 3][ns + n] = kv.w;
        }
    }

    // qsum partial over valid rows (active atoms all have mask = 1)
    {
        const int d = tid & 127, h = tid >> 7;
        float acc_q = 0.0f;
        #pragma unroll 8
        for (int n = h * 32; n < h * 32 + 32; n++)
            acc_q += validS[n] * Qs[n * QSTRIDE + d];
        partQ[h][d] = acc_q;
    }
    __syncthreads();
    if (tid < DIMP)
        g_qsum_part[mt][tid] = partQ[0][tid] + partQ[1][tid] + partQ[2][tid] + partQ[3][tid];

    // diag[n] = q[n] . k[n]  (compacted; junk beyond cnt is never read)
    #pragma unroll
    for (int rr = 0; rr < 8; rr++) {
        const int n = warp * 8 + rr;
        const float4 q4 = *(const float4*)(&Qs[n * QSTRIDE + lane * 4]);
        const float4 k4 = *(const float4*)(&Ks[n * QSTRIDE + lane * 4]);
        float s = q4.x * k4.x + q4.y * k4.y + q4.z * k4.z + q4.w * k4.w;
        #pragma unroll
        for (int o = 16; o; o >>= 1) s += __shfl_down_sync(0xffffffffu, s, o);
        if (lane == 0) g_diag[(size_t)mt * 128 + n] = s;
    }
    #undef FETCH
    #undef CVT_STORE
}

// ---------------------------------------------------------------------------
// Block reductions for 1024 threads (32 warps)
// ---------------------------------------------------------------------------
__device__ __forceinline__ float block_reduce_sum32(float v, float* red) {
    int lane = threadIdx.x & 31, warp = threadIdx.x >> 5;
    #pragma unroll
    for (int o = 16; o; o >>= 1) v += __shfl_down_sync(0xffffffffu, v, o);
    if (lane == 0) red[warp] = v;
    __syncthreads();
    if (warp == 0) {
        v = red[lane];
        #pragma unroll
        for (int o = 16; o; o >>= 1) v += __shfl_down_sync(0xffffffffu, v, o);
        if (lane == 0) red[32] = v;
    }
    __syncthreads();
    float r = red[32];
    __syncthreads();
    return r;
}

__device__ __forceinline__ float block_reduce_max32(float v, float* red) {
    int lane = threadIdx.x & 31, warp = threadIdx.x >> 5;
    #pragma unroll
    for (int o = 16; o; o >>= 1) v = fmaxf(v, __shfl_down_sync(0xffffffffu, v, o));
    if (lane == 0) red[warp] = v;
    __syncthreads();
    if (warp == 0) {
        v = red[lane];
        #pragma unroll
        for (int o = 16; o; o >>= 1) v = fmaxf(v, __shfl_down_sync(0xffffffffu, v, o));
        if (lane == 0) red[32] = v;
    }
    __syncthreads();
    float r = red[32];
    __syncthreads();
    return r;
}

// ---------------------------------------------------------------------------
// attn_fused: grid BATCH, 1024 threads. Compacted agg/softmax/context.
// Inactive atoms get attn = 0 (pre-zeroed, then active scattered via idx).
// ---------------------------------------------------------------------------
__global__ __launch_bounds__(1024)
void attn_fused_kernel(float* __restrict__ out) {
    const int b = blockIdx.x, tid = threadIdx.x;
    const int lane = tid & 31, warp = tid >> 5;
    const int n = tid & 511, half = tid >> 9;      // compacted slot, d-half
    const int cnt = g_cnt[b];
    __shared__ float qs[DIMP];
    __shared__ float agg2[2][NATOM];
    __shared__ float aw[NATOM];
    __shared__ float red[33];

    // zero the attn output (inactive atoms stay 0); ordered by __syncthreads
    if (tid < NATOM) out[(size_t)b * NATOM + tid] = 0.0f;

    if (tid < DIMP) {
        qs[tid] = g_qsum_part[b * 4 + 0][tid] + g_qsum_part[b * 4 + 1][tid]
                + g_qsum_part[b * 4 + 2][tid] + g_qsum_part[b * 4 + 3][tid];
    }
    __syncthreads();

    const float* __restrict__ Kt = &g_Kt[b][0][0];   // [128][512] compacted

    // agg partial: this thread sums d in [half*64, half*64+64) for slot n
    {
        float acc = 0.0f;
        const int d0 = half * 64;
        #pragma unroll 8
        for (int d = d0; d < d0 + 64; d++)
            acc = fmaf(Kt[d * NATOM + n], qs[d], acc);
        agg2[half][n] = acc;
    }
    __syncthreads();

    // combine; active slots are exactly tid < cnt (all have mask = 1)
    const int active = (tid < cnt);
    float v = 0.0f;
    if (active)
        v = agg2[0][tid] + agg2[1][tid] - g_diag[(size_t)b * 512 + tid];

    // normalize over atoms, masked softmax (inactive contribute exact zeros)
    const float total = block_reduce_sum32(v * v, red);
    const float nrm = sqrtf(total);
    float x = active ? (v / nrm) : -INFINITY;
    const float mx = block_reduce_max32(x, red);
    float e = active ? expf(x - mx) : 0.0f;
    const float denom = block_reduce_sum32(e, red);
    if (tid < NATOM) aw[tid] = 0.0f;
    __syncthreads();
    if (active) {
        const float attn = e / denom;
        out[(size_t)b * NATOM + g_idx[b][tid]] = attn;
        aw[tid] = attn;
    }
    __syncthreads();

    // context[d] = sum_n aw[n] * Kt[d][n]; 32 warps x 4 d-rows
    #pragma unroll
    for (int r = 0; r < 4; r++) {
        const int d = warp * 4 + r;
        const float* row = Kt + d * NATOM;
        float s = 0.0f;
        #pragma unroll
        for (int j = 0; j < 4; j++) {
            const float4 k4 = *(const float4*)(row + j * 128 + lane * 4);
            const float4 a4 = *(const float4*)(&aw[j * 128 + lane * 4]);
            s += k4.x * a4.x + k4.y * a4.y + k4.z * a4.z + k4.w * a4.w;
        }
        #pragma unroll
        for (int o = 16; o; o >>= 1) s += __shfl_down_sync(0xffffffffu, s, o);
        if (lane == 0) out[(size_t)BATCH * NATOM + (size_t)b * DIMP + d] = s;
    }
}

// ---------------------------------------------------------------------------
extern "C" void kernel_launch(void* const* d_in, const int* in_sizes, int n_in,
                              void* d_out, int out_size) {
    const float* atom_query = (const float*)d_in[0];
    const float* mask       = (const float*)d_in[1];
    const float* Wq         = (const float*)d_in[2];
    const float* bq         = (const float*)d_in[3];
    const float* Wk         = (const float*)d_in[4];
    const float* bk         = (const float*)d_in[5];
    float* out = (float*)d_out;

    static int smem_set = 0;
    if (!smem_set) {
        cudaFuncSetAttribute(gemm_fused_kernel,
                             cudaFuncAttributeMaxDynamicSharedMemorySize, DSMEM_BYTES);
        smem_set = 1;
    }

    compact_kernel<<<BATCH, 512>>>(mask);
    gemm_fused_kernel<<<NTILES, 512, DSMEM_BYTES>>>(atom_query, Wq, Wk, bq, bk);
    attn_fused_kernel<<<BATCH, 1024>>>(out);
}

// round 14
// speedup vs baseline: 1.1882x; 1.1882x over previous
#include <cuda_runtime.h>
#include <cuda_bf16.h>
#include <mma.h>
#include <math.h>
#include <stdint.h>

using namespace nvcuda;

// Problem constants
#define BATCH 64
#define NATOM 512
#define DFEAT 128
#define DIMP  128
#define MROWS (BATCH * NATOM)      // 32768
#define NCOLS (2 * DIMP)           // 256 (q | k fused in n)
#define TILE_M 64
#define SLOTS  8                   // compacted 64-row slots per batch
#define NTILES (BATCH * SLOTS)     // 512

// smem strides (elements)
#define ASTRIDE 40                 // 32 + 8 pad (bf16)
#define BSTRIDE 264                // 256 + 8 pad (bf16)
#define QSTRIDE 132                // 128 + 4 pad (fp32)

// stage layout (bytes, per buffer)
#define OFF_AH   0
#define OFF_AL   (TILE_M * ASTRIDE * 2)                 // 5120
#define OFF_BH   (OFF_AL + TILE_M * ASTRIDE * 2)        // 10240
#define OFF_BL   (OFF_BH + 32 * BSTRIDE * 2)            // 27136
#define STAGE_BYTES (OFF_BL + 32 * BSTRIDE * 2)         // 44032
#define EPI_BYTES (2 * TILE_M * QSTRIDE * 4)            // 67584 (Qs | Ks)
#define PIPE_BYTES (2 * STAGE_BYTES)                    // 88064
#define DSMEM_BYTES (EPI_BYTES > PIPE_BYTES ? EPI_BYTES : PIPE_BYTES)

// Device scratch
__device__ float g_Kt[BATCH][DIMP][NATOM];             // compacted K^T, 16 MB
__device__ float g_qsum_part[NTILES][DIMP];            // 256 KB
__device__ float g_diag[MROWS];                        // compacted, 128 KB
__device__ int   g_idx[BATCH][NATOM];                  // active-atom lists
__device__ int   g_cnt[BATCH];

// ---------------------------------------------------------------------------
// compact: per batch, order-preserving list of active (mask=1) atoms.
// ---------------------------------------------------------------------------
__global__ __launch_bounds__(512)
void compact_kernel(const float* __restrict__ mask) {
    const int b = blockIdx.x, tid = threadIdx.x;
    const int lane = tid & 31, warp = tid >> 5;
    __shared__ int wcnt[16];
    __shared__ int woff[16];

    const int m = mask[(size_t)b * NATOM + tid] > 0.5f ? 1 : 0;
    const unsigned bal = __ballot_sync(0xffffffffu, m);
    if (lane == 0) wcnt[warp] = __popc(bal);
    __syncthreads();
    if (tid == 0) {
        int s = 0;
        #pragma unroll
        for (int i = 0; i < 16; i++) { woff[i] = s; s += wcnt[i]; }
        g_cnt[b] = s;
    }
    __syncthreads();
    if (m) {
        int pos = woff[warp] + __popc(bal & ((1u << lane) - 1u));
        g_idx[b][pos] = tid;
    }
}

// ---------------------------------------------------------------------------
// Fused GEMM over COMPACTED rows: 512 slot-CTAs x 512 threads.
// Tile 64m x 256n, K=3x128 bf16 split, double-buffered. Empty slots exit.
// Epilogue: compacted K^T, qsum partials, diag.
// ---------------------------------------------------------------------------
__global__ __launch_bounds__(512, 1)
void gemm_fused_kernel(const float* __restrict__ A,
                       const float* __restrict__ Wq, const float* __restrict__ Wk,
                       const float* __restrict__ bq, const float* __restrict__ bk) {
    extern __shared__ char dsm[];
    __shared__ float validS[TILE_M];
    __shared__ int   idxS[TILE_M];
    __shared__ float partQ[4][DIMP];

    const int tid  = threadIdx.x;
    const int warp = tid >> 5;
    const int lane = tid & 31;
    const int mt   = blockIdx.x;
    const int b    = mt >> 3;
    const int slot = mt & 7;
    const int cnt  = g_cnt[b];

    // empty slot: publish zero qsum partial, leave
    if (slot * TILE_M >= cnt) {
        if (tid < DIMP) g_qsum_part[mt][tid] = 0.0f;
        return;
    }

    if (tid < TILE_M) {
        int j = slot * TILE_M + tid;
        int ok = j < cnt;
        idxS[tid]   = ok ? g_idx[b][j] : g_idx[b][0];   // clamp (finite junk)
        validS[tid] = ok ? 1.0f : 0.0f;
    }

    const int wm = (warp >> 2) * 16;      // 4 warp-rows of 16
    const int wn = (warp & 3) * 64;       // 4 warp-cols of 64

    // --- accumulator init with bias (replicated 16-row tile in dsm) ---
    float* biasT = (float*)dsm;           // 16 x 256
    for (int i = tid; i < 16 * NCOLS; i += 512) {
        int col = i & 255;
        biasT[i] = (col < DIMP) ? bq[col] : bk[col - DIMP];
    }
    __syncthreads();

    wmma::fragment<wmma::accumulator, 16, 16, 16, float> acc[4];
    #pragma unroll
    for (int j = 0; j < 4; j++)
        wmma::load_matrix_sync(acc[j], biasT + wn + j * 16, NCOLS, wmma::mem_row_major);
    __syncthreads();

    // loader index precompute (A rows gathered through idxS)
    const int ar0 = tid >> 3, ac0 = (tid & 7) * 4;      // 64 rows x 8 thr/row
    const float* rp0 = A + ((size_t)b * NATOM + idxS[ar0]) * DFEAT;
    int brr[4], bcc[4];
    #pragma unroll
    for (int v = 0; v < 4; v++) {
        int f = tid + v * 512;
        brr[v] = f >> 6;
        bcc[v] = (f & 63) * 4;
    }

    float4 pa, pb[4];
    #define FETCH(kc)                                                                   \
        do {                                                                            \
            pa = *(const float4*)(rp0 + (kc) * 32 + ac0);                               \
            _Pragma("unroll")                                                           \
            for (int v = 0; v < 4; v++) {                                               \
                int k = (kc) * 32 + brr[v];                                             \
                pb[v] = (bcc[v] < DIMP)                                                 \
                    ? *(const float4*)(Wq + (size_t)k * DIMP + bcc[v])                  \
                    : *(const float4*)(Wk + (size_t)k * DIMP + (bcc[v] - DIMP));        \
            }                                                                           \
        } while (0)

    #define CVT_STORE(buf)                                                              \
        do {                                                                            \
            __nv_bfloat16* AhS = (__nv_bfloat16*)(dsm + (buf) * STAGE_BYTES + OFF_AH);  \
            __nv_bfloat16* AlS = (__nv_bfloat16*)(dsm + (buf) * STAGE_BYTES + OFF_AL);  \
            __nv_bfloat16* BhS = (__nv_bfloat16*)(dsm + (buf) * STAGE_BYTES + OFF_BH);  \
            __nv_bfloat16* BlS = (__nv_bfloat16*)(dsm + (buf) * STAGE_BYTES + OFF_BL);  \
            {                                                                           \
                float vv[4] = {pa.x, pa.y, pa.z, pa.w};                                 \
                uint16_t h[4], l[4];                                                    \
                _Pragma("unroll")                                                       \
                for (int i = 0; i < 4; i++) {                                           \
                    __nv_bfloat16 hb = __float2bfloat16(vv[i]);                         \
                    __nv_bfloat16 lb = __float2bfloat16(vv[i] - __bfloat162float(hb));  \
                    h[i] = __bfloat16_as_ushort(hb);                                    \
                    l[i] = __bfloat16_as_ushort(lb);                                    \
                }                                                                       \
                *(uint2*)(&AhS[ar0 * ASTRIDE + ac0]) =                                  \
                    make_uint2(((uint32_t)h[1] << 16) | h[0], ((uint32_t)h[3] << 16) | h[2]); \
                *(uint2*)(&AlS[ar0 * ASTRIDE + ac0]) =                                  \
                    make_uint2(((uint32_t)l[1] << 16) | l[0], ((uint32_t)l[3] << 16) | l[2]); \
            }                                                                           \
            _Pragma("unroll")                                                           \
            for (int v = 0; v < 4; v++) {                                               \
                float vv[4] = {pb[v].x, pb[v].y, pb[v].z, pb[v].w};                     \
                uint16_t h[4], l[4];                                                    \
                _Pragma("unroll")                                                       \
                for (int i = 0; i < 4; i++) {                                           \
                    __nv_bfloat16 hb = __float2bfloat16(vv[i]);                         \
                    __nv_bfloat16 lb = __float2bfloat16(vv[i] - __bfloat162float(hb));  \
                    h[i] = __bfloat16_as_ushort(hb);                                    \
                    l[i] = __bfloat16_as_ushort(lb);                                    \
                }                                                                       \
                *(uint2*)(&BhS[brr[v] * BSTRIDE + bcc[v]]) =                            \
                    make_uint2(((uint32_t)h[1] << 16) | h[0], ((uint32_t)h[3] << 16) | h[2]); \
                *(uint2*)(&BlS[brr[v] * BSTRIDE + bcc[v]]) =                            \
                    make_uint2(((uint32_t)l[1] << 16) | l[0], ((uint32_t)l[3] << 16) | l[2]); \
            }                                                                           \
        } while (0)

    // --- pipelined mainloop: 4 chunks of k=32, 3 passes each ---
    FETCH(0);
    CVT_STORE(0);
    __syncthreads();

    #pragma unroll
    for (int kc = 0; kc < 4; kc++) {
        const int cur = kc & 1;
        if (kc < 3) FETCH(kc + 1);

        const __nv_bfloat16* AhS = (const __nv_bfloat16*)(dsm + cur * STAGE_BYTES + OFF_AH);
        const __nv_bfloat16* AlS = (const __nv_bfloat16*)(dsm + cur * STAGE_BYTES + OFF_AL);
        const __nv_bfloat16* BhS = (const __nv_bfloat16*)(dsm + cur * STAGE_BYTES + OFF_BH);
        const __nv_bfloat16* BlS = (const __nv_bfloat16*)(dsm + cur * STAGE_BYTES + OFF_BL);

        #pragma unroll
        for (int pass = 0; pass < 3; pass++) {
            const __nv_bfloat16* Ap = (pass == 1) ? AlS : AhS;
            const __nv_bfloat16* Bp = (pass == 2) ? BlS : BhS;
            #pragma unroll
            for (int kk = 0; kk < 32; kk += 16) {
                wmma::fragment<wmma::matrix_a, 16, 16, 16, __nv_bfloat16, wmma::row_major> af;
                wmma::fragment<wmma::matrix_b, 16, 16, 16, __nv_bfloat16, wmma::row_major> bf[4];
                wmma::load_matrix_sync(af, Ap + wm * ASTRIDE + kk, ASTRIDE);
                #pragma unroll
                for (int j = 0; j < 4; j++)
                    wmma::load_matrix_sync(bf[j], Bp + kk * BSTRIDE + wn + j * 16, BSTRIDE);
                #pragma unroll
                for (int j = 0; j < 4; j++)
                    wmma::mma_sync(acc[j], af, bf[j], acc[j]);
            }
        }

        if (kc < 3) CVT_STORE(1 - cur);
        __syncthreads();
    }

    // --- epilogue: overlay Qs|Ks in dsm ---
    float* Qs = (float*)dsm;                       // 64 x QSTRIDE
    float* Ks = Qs + TILE_M * QSTRIDE;
    #pragma unroll
    for (int j = 0; j < 4; j++) {
        int n = wn + j * 16;
        float* t = (n < DIMP) ? (Qs + wm * QSTRIDE + n)
                              : (Ks + wm * QSTRIDE + (n - DIMP));
        wmma::store_matrix_sync(t, acc[j], QSTRIDE, wmma::mem_row_major);
    }
    __syncthreads();

    // compacted K^T write: batch b, compacted slots ns..ns+63
    {
        const int ns = slot * TILE_M;
        #pragma unroll
        for (int v = 0; v < 4; v++) {
            int f = v * 512 + tid;        // 0..2047
            int n = f & 63;
            int d4 = (f >> 6) * 4;        // 0..124
            float4 kv = *(float4*)(&Ks[n * QSTRIDE + d4]);
            g_Kt[b][d4 + 0][ns + n] = kv.x;
            g_Kt[b][d4 + 1][ns + n] = kv.y;
            g_Kt[b][d4 + 2][ns + n] = kv.z;
            g_Kt[b][d4 + 3][ns + n] = kv.w;
        }
    }

    // qsum partial over valid rows (4 groups of 16 rows)
    {
        const int d = tid & 127, h = tid >> 7;
        float acc_q = 0.0f;
        #pragma unroll 8
        for (int n = h * 16; n < h * 16 + 16; n++)
            acc_q += validS[n] * Qs[n * QSTRIDE + d];
        partQ[h][d] = acc_q;
    }
    __syncthreads();
    if (tid < DIMP)
        g_qsum_part[mt][tid] = partQ[0][tid] + partQ[1][tid] + partQ[2][tid] + partQ[3][tid];

    // diag[n] = q[n] . k[n]  (16 warps x 4 rows; junk beyond cnt unread)
    #pragma unroll
    for (int rr = 0; rr < 4; rr++) {
        const int n = warp * 4 + rr;
        const float4 q4 = *(const float4*)(&Qs[n * QSTRIDE + lane * 4]);
        const float4 k4 = *(const float4*)(&Ks[n * QSTRIDE + lane * 4]);
        float s = q4.x * k4.x + q4.y * k4.y + q4.z * k4.z + q4.w * k4.w;
        #pragma unroll
        for (int o = 16; o; o >>= 1) s += __shfl_down_sync(0xffffffffu, s, o);
        if (lane == 0) g_diag[(size_t)b * NATOM + slot * TILE_M + n] = s;
    }
    #undef FETCH
    #undef CVT_STORE
}

// ---------------------------------------------------------------------------
// Block reductions for 1024 threads (32 warps)
// ---------------------------------------------------------------------------
__device__ __forceinline__ float block_reduce_sum32(float v, float* red) {
    int lane = threadIdx.x & 31, warp = threadIdx.x >> 5;
    #pragma unroll
    for (int o = 16; o; o >>= 1) v += __shfl_down_sync(0xffffffffu, v, o);
    if (lane == 0) red[warp] = v;
    __syncthreads();
    if (warp == 0) {
        v = red[lane];
        #pragma unroll
        for (int o = 16; o; o >>= 1) v += __shfl_down_sync(0xffffffffu, v, o);
        if (lane == 0) red[32] = v;
    }
    __syncthreads();
    float r = red[32];
    __syncthreads();
    return r;
}

__device__ __forceinline__ float block_reduce_max32(float v, float* red) {
    int lane = threadIdx.x & 31, warp = threadIdx.x >> 5;
    #pragma unroll
    for (int o = 16; o; o >>= 1) v = fmaxf(v, __shfl_down_sync(0xffffffffu, v, o));
    if (lane == 0) red[warp] = v;
    __syncthreads();
    if (warp == 0) {
        v = red[lane];
        #pragma unroll
        for (int o = 16; o; o >>= 1) v = fmaxf(v, __shfl_down_sync(0xffffffffu, v, o));
        if (lane == 0) red[32] = v;
    }
    __syncthreads();
    float r = red[32];
    __syncthreads();
    return r;
}

// ---------------------------------------------------------------------------
// attn_fused: grid BATCH, 1024 threads. Compacted agg/softmax/context.
// ---------------------------------------------------------------------------
__global__ __launch_bounds__(1024)
void attn_fused_kernel(float* __restrict__ out) {
    const int b = blockIdx.x, tid = threadIdx.x;
    const int lane = tid & 31, warp = tid >> 5;
    const int n = tid & 511, half = tid >> 9;      // compacted slot, d-half
    const int cnt = g_cnt[b];
    __shared__ float qs[DIMP];
    __shared__ float agg2[2][NATOM];
    __shared__ float aw[NATOM];
    __shared__ float red[33];

    // zero the attn output (inactive atoms stay 0)
    if (tid < NATOM) out[(size_t)b * NATOM + tid] = 0.0f;

    if (tid < DIMP) {
        float a = 0.0f;
        #pragma unroll
        for (int p = 0; p < SLOTS; p++) a += g_qsum_part[b * SLOTS + p][tid];
        qs[tid] = a;
    }
    __syncthreads();

    const float* __restrict__ Kt = &g_Kt[b][0][0];   // [128][512] compacted

    // agg partial: this thread sums d in [half*64, half*64+64) for slot n
    {
        float acc = 0.0f;
        const int d0 = half * 64;
        #pragma unroll 8
        for (int d = d0; d < d0 + 64; d++)
            acc = fmaf(Kt[d * NATOM + n], qs[d], acc);
        agg2[half][n] = acc;
    }
    __syncthreads();

    // combine; active slots are exactly tid < cnt
    const int active = (tid < cnt);
    float v = 0.0f;
    if (active)
        v = agg2[0][tid] + agg2[1][tid] - g_diag[(size_t)b * NATOM + tid];

    // normalize over atoms, masked softmax
    const float total = block_reduce_sum32(v * v, red);
    const float nrm = sqrtf(total);
    float x = active ? (v / nrm) : -INFINITY;
    const float mx = block_reduce_max32(x, red);
    float e = active ? expf(x - mx) : 0.0f;
    const float denom = block_reduce_sum32(e, red);
    if (tid < NATOM) aw[tid] = 0.0f;
    __syncthreads();
    if (active) {
        const float attn = e / denom;
        out[(size_t)b * NATOM + g_idx[b][tid]] = attn;
        aw[tid] = attn;
    }
    __syncthreads();

    // context[d] = sum_n aw[n] * Kt[d][n]; 32 warps x 4 d-rows
    #pragma unroll
    for (int r = 0; r < 4; r++) {
        const int d = warp * 4 + r;
        const float* row = Kt + d * NATOM;
        float s = 0.0f;
        #pragma unroll
        for (int j = 0; j < 4; j++) {
            const float4 k4 = *(const float4*)(row + j * 128 + lane * 4);
            const float4 a4 = *(const float4*)(&aw[j * 128 + lane * 4]);
            s += k4.x * a4.x + k4.y * a4.y + k4.z * a4.z + k4.w * a4.w;
        }
        #pragma unroll
        for (int o = 16; o; o >>= 1) s += __shfl_down_sync(0xffffffffu, s, o);
        if (lane == 0) out[(size_t)BATCH * NATOM + (size_t)b * DIMP + d] = s;
    }
}

// ---------------------------------------------------------------------------
extern "C" void kernel_launch(void* const* d_in, const int* in_sizes, int n_in,
                              void* d_out, int out_size) {
    const float* atom_query = (const float*)d_in[0];
    const float* mask       = (const float*)d_in[1];
    const float* Wq         = (const float*)d_in[2];
    const float* bq         = (const float*)d_in[3];
    const float* Wk         = (const float*)d_in[4];
    const float* bk         = (const float*)d_in[5];
    float* out = (float*)d_out;

    static int smem_set = 0;
    if (!smem_set) {
        cudaFuncSetAttribute(gemm_fused_kernel,
                             cudaFuncAttributeMaxDynamicSharedMemorySize, DSMEM_BYTES);
        smem_set = 1;
    }

    compact_kernel<<<BATCH, 512>>>(mask);
    gemm_fused_kernel<<<NTILES, 512, DSMEM_BYTES>>>(atom_query, Wq, Wk, bq, bk);
    attn_fused_kernel<<<BATCH, 1024>>>(out);
}